// round 6
// baseline (speedup 1.0000x reference)
#include <cuda_runtime.h>
#include <math.h>

#define N_NODES 4096
#define H 256
#define E_EDGES 131072

typedef unsigned long long u64;

__device__ __forceinline__ void ffma2(u64 &d, u64 a, u64 b) {
    asm("fma.rn.f32x2 %0, %1, %2, %0;" : "+l"(d) : "l"(a), "l"(b));
}
__device__ __forceinline__ void mul2(u64 &d, u64 a) {
    asm("mul.rn.f32x2 %0, %0, %1;" : "+l"(d) : "l"(a));
}
__device__ __forceinline__ u64 bcast2(float x) {
    u64 r; asm("mov.b64 %0, {%1, %1};" : "=l"(r) : "f"(x)); return r;
}
__device__ __forceinline__ float2 unpk(u64 v) {
    float2 r; asm("mov.b64 {%0, %1}, %2;" : "=f"(r.x), "=f"(r.y) : "l"(v)); return r;
}

// ---------------- scratch ----------------
__device__ float g_h[N_NODES*H];
__device__ float g_agg[N_NODES*H];
__device__ float g_tmp[N_NODES*H];
__device__ float g_ca[N_NODES*H];
__device__ float g_cb[N_NODES*H];
__device__ float g_qkv[N_NODES*6*H];
__device__ float g_qkt[8*128*N_NODES];   // [qk*4+head][d][n] transposed Q,K
__device__ float g_attn[N_NODES*2*H];
__device__ float g_o[N_NODES*2*H];
__device__ float g_o2[N_NODES*2*H];
__device__ float g_sagew[6*H*2*H];
__device__ float g_convw[3*H*3*H];
__device__ int   g_cnt[N_NODES];
__device__ int   g_fillp[N_NODES];
__device__ int   g_off[N_NODES+1];
__device__ int   g_csrs[E_EDGES];
__device__ float g_degf[N_NODES];

// ---------------- CSR build ----------------
__global__ void k_zero() {
    int i = blockIdx.x*256 + threadIdx.x;
    if (i < N_NODES) { g_cnt[i] = 0; g_fillp[i] = 0; }
}
__global__ void k_count(const int* __restrict__ dst) {
    int e = blockIdx.x*256 + threadIdx.x;
    if (e < E_EDGES) atomicAdd(&g_cnt[dst[e]], 1);
}
__global__ void k_scan() {
    __shared__ int ps[1024];
    int t = threadIdx.x;
    int c[4]; int s = 0;
    #pragma unroll
    for (int l = 0; l < 4; l++) { c[l] = g_cnt[t*4+l]; s += c[l]; }
    ps[t] = s;
    __syncthreads();
    for (int d = 1; d < 1024; d <<= 1) {
        int v = (t >= d) ? ps[t-d] : 0;
        __syncthreads();
        ps[t] += v;
        __syncthreads();
    }
    int base = ps[t] - s;
    #pragma unroll
    for (int l = 0; l < 4; l++) {
        g_off[t*4+l] = base;
        base += c[l];
        g_degf[t*4+l] = (float)max(c[l], 1);
    }
    if (t == 1023) g_off[N_NODES] = ps[1023];
}
__global__ void k_fill(const int* __restrict__ src, const int* __restrict__ dst) {
    int e = blockIdx.x*256 + threadIdx.x;
    if (e < E_EDGES) {
        int d = dst[e];
        int p = atomicAdd(&g_fillp[d], 1);
        g_csrs[g_off[d] + p] = src[e];
    }
}

// ---------------- weight packing ----------------
__global__ void k_packsage(const float* __restrict__ wl, const float* __restrict__ wr,
                           float* __restrict__ out) {
    int idx = blockIdx.x*256 + threadIdx.x;
    if (idx < 6*H*2*H) {
        int c = idx & 511;
        int r = idx >> 9;
        out[idx] = (c < H) ? wl[r*H + c] : wr[r*H + (c - H)];
    }
}
__global__ void k_packconv(const float* __restrict__ w, float* __restrict__ out) {
    int idx = blockIdx.x*256 + threadIdx.x;
    if (idx < 3*H*3*H) {
        int c = idx % 768;
        int r = idx / 768;
        int k = c >> 8;
        int i = c & 255;
        out[idx] = w[(size_t)(r*H + i)*3 + k];
    }
}

// ---------------- Q/K transpose: qkv[n][qk*512+h*128+d] -> qkt[(qk*4+h)*128+d][n] ----
__global__ __launch_bounds__(256) void k_qkT(const float* __restrict__ qkv,
                                             float* __restrict__ qkt) {
    __shared__ float tile[32][33];
    int nt = blockIdx.x*32;
    int dt = blockIdx.y*32;                 // global transposed row 0..1023
    int g  = dt >> 7;                       // which of 8 (qk,head) maps
    int cb = (g >> 2)*512 + (g & 3)*128 + (dt & 127);  // qkv column base
    int tx = threadIdx.x & 31, ty = threadIdx.x >> 5;  // 32 x 8
    #pragma unroll
    for (int i = 0; i < 4; i++)
        tile[ty + i*8][tx] = qkv[(size_t)(nt + ty + i*8)*1536 + cb + tx];
    __syncthreads();
    #pragma unroll
    for (int i = 0; i < 4; i++)
        qkt[(size_t)(dt + ty + i*8)*N_NODES + nt + tx] = tile[tx][ty + i*8];
}

// ---------------- mean aggregation ----------------
__global__ __launch_bounds__(256) void k_agg(const float* __restrict__ h,
                                             float* __restrict__ agg) {
    int n = blockIdx.x;
    int f = threadIdx.x;
    int s = g_off[n], e = g_off[n+1];
    __shared__ int nb[256];
    float acc = 0.f;
    for (int base = s; base < e; base += 256) {
        int m = min(256, e - base);
        if (f < m) nb[f] = g_csrs[base + f];
        __syncthreads();
        for (int j = 0; j < m; j++)
            acc += h[(size_t)nb[j]*H + f];
        __syncthreads();
    }
    agg[(size_t)n*H + f] = acc / g_degf[n];
}

// ---------------- segmented SGEMM (f32x2): BM=64, BN=128, BK=16 ----------------
#define BM 64
#define BN 128
#define BK 16
#define AST 68
#define BST 132

__global__ __launch_bounds__(256) void k_sgemm(
    const float* __restrict__ A0, int ld0, int sh0,
    const float* __restrict__ A1, int ld1, int sh1,
    const float* __restrict__ A2, int ld2, int sh2,
    const float* __restrict__ B, int ldb,
    float* __restrict__ C, int ldc,
    int M, int K, int Ncols,
    const float* __restrict__ bias)
{
    __shared__ float As[BK*AST];
    __shared__ float Bs[BK*BST];
    int bm = blockIdx.y * BM;
    int bn = blockIdx.x * BN;
    int t  = threadIdx.x;
    int m0  = (t >> 4) * 4;
    int n0a = (t & 15) * 4;
    int n0b = n0a + 64;

    u64 acc2[2][8];
    #pragma unroll
    for (int p = 0; p < 2; p++)
        #pragma unroll
        for (int c = 0; c < 8; c++) acc2[p][c] = 0ULL;

    for (int k0 = 0; k0 < K; k0 += BK) {
        int seg = k0 >> 8;
        const float* A = (seg == 0) ? A0 : (seg == 1) ? A1 : A2;
        int lda = (seg == 0) ? ld0 : (seg == 1) ? ld1 : ld2;
        int sh  = (seg == 0) ? sh0 : (seg == 1) ? sh1 : sh2;
        int kc  = k0 & 255;
        #pragma unroll
        for (int l = 0; l < 4; l++) {
            int flat = t + l*256;
            int ar = flat >> 4, ak = flat & 15;
            int gr = bm + ar + sh;
            As[ak*AST + ar] = (gr >= 0 && gr < M) ? A[(size_t)gr*lda + kc + ak] : 0.f;
        }
        #pragma unroll
        for (int l = 0; l < 8; l++) {
            int flat = t + l*256;
            int br = flat >> 4, bk = flat & 15;
            int gc = bn + br;
            Bs[bk*BST + br] = (gc < Ncols) ? B[(size_t)gc*ldb + k0 + bk] : 0.f;
        }
        __syncthreads();
        #pragma unroll
        for (int kk = 0; kk < BK; kk++) {
            ulonglong2 av = *(const ulonglong2*)&As[kk*AST + m0];
            float4 b0 = *(const float4*)&Bs[kk*BST + n0a];
            float4 b1 = *(const float4*)&Bs[kk*BST + n0b];
            u64 ap[2] = {av.x, av.y};
            u64 bb[8] = {bcast2(b0.x), bcast2(b0.y), bcast2(b0.z), bcast2(b0.w),
                         bcast2(b1.x), bcast2(b1.y), bcast2(b1.z), bcast2(b1.w)};
            #pragma unroll
            for (int p = 0; p < 2; p++)
                #pragma unroll
                for (int c = 0; c < 8; c++)
                    ffma2(acc2[p][c], ap[p], bb[c]);
        }
        __syncthreads();
    }

    int ca = bn + n0a, cb2 = bn + n0b;
    #pragma unroll
    for (int p = 0; p < 2; p++) {
        int r0 = bm + m0 + 2*p;
        float2 u0 = unpk(acc2[p][0]), u1 = unpk(acc2[p][1]);
        float2 u2 = unpk(acc2[p][2]), u3 = unpk(acc2[p][3]);
        float2 u4 = unpk(acc2[p][4]), u5 = unpk(acc2[p][5]);
        float2 u6 = unpk(acc2[p][6]), u7 = unpk(acc2[p][7]);
        if (ca < Ncols) {
            float4 bs = *(const float4*)&bias[ca];
            *(float4*)&C[(size_t)r0*ldc + ca] =
                make_float4(u0.x+bs.x, u1.x+bs.y, u2.x+bs.z, u3.x+bs.w);
            *(float4*)&C[(size_t)(r0+1)*ldc + ca] =
                make_float4(u0.y+bs.x, u1.y+bs.y, u2.y+bs.z, u3.y+bs.w);
        }
        if (cb2 < Ncols) {
            float4 bs = *(const float4*)&bias[cb2];
            *(float4*)&C[(size_t)r0*ldc + cb2] =
                make_float4(u4.x+bs.x, u5.x+bs.y, u6.x+bs.z, u7.x+bs.w);
            *(float4*)&C[(size_t)(r0+1)*ldc + cb2] =
                make_float4(u4.y+bs.x, u5.y+bs.y, u6.y+bs.z, u7.y+bs.w);
        }
    }
}

// ---------------- LayerNorm / activation ----------------
#define F_LN       1
#define F_POSTRELU 2
#define F_RES      4
#define F_PRERELU  8

__global__ __launch_bounds__(256) void k_ln(
    const float* __restrict__ x, const float* __restrict__ g, const float* __restrict__ b,
    const float* __restrict__ res, float* __restrict__ out, int W, int flags)
{
    __shared__ float rs[8], rq[8];
    __shared__ float s_mean, s_rstd;
    int row = blockIdx.x, t = threadIdx.x;
    const float* xr = x + (size_t)row*W;
    int two = (W == 512);
    float v0 = xr[t];
    float v1 = two ? xr[t + 256] : 0.f;
    if (flags & F_PRERELU) { v0 = fmaxf(v0, 0.f); v1 = fmaxf(v1, 0.f); }
    float s = v0 + v1, sq = v0*v0 + v1*v1;
    #pragma unroll
    for (int o = 16; o > 0; o >>= 1) {
        s  += __shfl_xor_sync(0xffffffff, s,  o);
        sq += __shfl_xor_sync(0xffffffff, sq, o);
    }
    int warp = t >> 5, lane = t & 31;
    if (lane == 0) { rs[warp] = s; rq[warp] = sq; }
    __syncthreads();
    if (t == 0) {
        float S = 0.f, Q = 0.f;
        #pragma unroll
        for (int w = 0; w < 8; w++) { S += rs[w]; Q += rq[w]; }
        float mean = S / (float)W;
        float var = fmaxf(Q / (float)W - mean*mean, 0.f);
        s_mean = mean;
        s_rstd = rsqrtf(var + 1e-5f);
    }
    __syncthreads();
    float mean = s_mean, rstd = s_rstd;

    float val = v0;
    if (flags & F_LN)       val = (val - mean)*rstd*g[t] + b[t];
    if (flags & F_POSTRELU) val = fmaxf(val, 0.f);
    if (flags & F_RES)      val += res[(size_t)row*W + t];
    out[(size_t)row*W + t] = val;

    if (two) {
        int c = t + 256;
        float val2 = v1;
        if (flags & F_LN)       val2 = (val2 - mean)*rstd*g[c] + b[c];
        if (flags & F_POSTRELU) val2 = fmaxf(val2, 0.f);
        if (flags & F_RES)      val2 += res[(size_t)row*W + c];
        out[(size_t)row*W + c] = val2;
    }
}

// ---------------- flash attention (f32x2): BQ=64, BKV=32 ----------------
// smem layout (floats): Qt[128][68] | Kt[128][36] | Vs[32][132] | Ss[64][36] | rowm/l/f[64]
// All row strides are multiples of 4 floats (16B) for aligned 128-bit accesses.
#define QTS 68
#define KTS 36
#define VS_ 132
#define SS_ 36
#define OFF_KT (128*QTS)
#define OFF_V  (OFF_KT + 128*KTS)
#define OFF_S  (OFF_V + 32*VS_)
#define OFF_R  (OFF_S + 64*SS_)
#define FLASH_SMEM ((OFF_R + 192)*4)

__global__ __launch_bounds__(256, 2) void k_flash(const float* __restrict__ qkv,
                                                  const float* __restrict__ qkt,
                                                  float* __restrict__ outp)
{
    extern __shared__ float sm[];
    float* Qt = sm;
    float* Kt = sm + OFF_KT;
    float* Vs = sm + OFF_V;
    float* Ss = sm + OFF_S;
    float* rowm = sm + OFF_R;
    float* rowl = rowm + 64;
    float* rowf = rowl + 64;

    int qb = blockIdx.x, head = blockIdx.y, t = threadIdx.x;
    int n0 = qb*64, coff = head*128;
    int kg = t & 15;
    int q0 = (t >> 4) * 4;       // 4 q rows (2 pairs)
    int k0 = 2*kg;               // QK: 2 k cols
    int pd0 = 4*kg, pd1 = 64 + 4*kg;  // PV: split d cols

    // load Q transposed tile: Qt[d][q] = qkt[(head*128+d)*4096 + n0+q]
    const float* Qg = qkt + (size_t)head*128*N_NODES + n0;
    #pragma unroll
    for (int l = 0; l < 8; l++) {
        int f4 = t + l*256;
        int r = f4 >> 4, c = f4 & 15;
        *(float4*)&Qt[r*QTS + c*4] = *(const float4*)&Qg[(size_t)r*N_NODES + c*4];
    }
    if (t < 64) { rowm[t] = -1e30f; rowl[t] = 0.f; }

    u64 oacc[4][4];
    #pragma unroll
    for (int i = 0; i < 4; i++)
        #pragma unroll
        for (int c = 0; c < 4; c++) oacc[i][c] = 0ULL;

    const float scale = 0.08838834764831845f;
    const float* Kg = qkt + (size_t)(4 + head)*128*N_NODES;

    for (int kb = 0; kb < 128; kb++) {
        __syncthreads();
        // load K tile [128 d][32 k] + V tile [32 n][128 d]
        #pragma unroll
        for (int l = 0; l < 4; l++) {
            int f4 = t + l*256;
            int r = f4 >> 3, c = f4 & 7;
            *(float4*)&Kt[r*KTS + c*4] =
                *(const float4*)&Kg[(size_t)r*N_NODES + kb*32 + c*4];
        }
        #pragma unroll
        for (int l = 0; l < 4; l++) {
            int f4 = t + l*256;
            int r = f4 >> 5, c = f4 & 31;
            *(float4*)&Vs[r*VS_ + c*4] =
                *(const float4*)&qkv[(size_t)(kb*32 + r)*1536 + 1024 + coff + c*4];
        }
        __syncthreads();
        // S = Q K^T
        u64 sacc[2][2] = {{0ULL,0ULL},{0ULL,0ULL}};
        #pragma unroll 4
        for (int d = 0; d < 128; d++) {
            ulonglong2 qv = *(const ulonglong2*)&Qt[d*QTS + q0];
            float2 kk2 = *(const float2*)&Kt[d*KTS + k0];
            u64 kb0 = bcast2(kk2.x), kb1 = bcast2(kk2.y);
            ffma2(sacc[0][0], qv.x, kb0); ffma2(sacc[0][1], qv.x, kb1);
            ffma2(sacc[1][0], qv.y, kb0); ffma2(sacc[1][1], qv.y, kb1);
        }
        #pragma unroll
        for (int p = 0; p < 2; p++)
            #pragma unroll
            for (int j = 0; j < 2; j++) {
                float2 u = unpk(sacc[p][j]);
                Ss[(q0 + 2*p    )*SS_ + k0 + j] = u.x*scale;
                Ss[(q0 + 2*p + 1)*SS_ + k0 + j] = u.y*scale;
            }
        __syncthreads();
        // online softmax: 4 threads per row, 8 cols each
        {
            int sr = t >> 2, c0 = (t & 3)*8;
            float4 a = *(float4*)&Ss[sr*SS_ + c0];
            float4 bvv = *(float4*)&Ss[sr*SS_ + c0 + 4];
            float mold = rowm[sr];
            float mx = fmaxf(fmaxf(fmaxf(a.x,a.y), fmaxf(a.z,a.w)),
                             fmaxf(fmaxf(bvv.x,bvv.y), fmaxf(bvv.z,bvv.w)));
            mx = fmaxf(mx, __shfl_xor_sync(0xffffffffu, mx, 1));
            mx = fmaxf(mx, __shfl_xor_sync(0xffffffffu, mx, 2));
            mx = fmaxf(mx, mold);
            a.x = __expf(a.x - mx); a.y = __expf(a.y - mx);
            a.z = __expf(a.z - mx); a.w = __expf(a.w - mx);
            bvv.x = __expf(bvv.x - mx); bvv.y = __expf(bvv.y - mx);
            bvv.z = __expf(bvv.z - mx); bvv.w = __expf(bvv.w - mx);
            float ls = (a.x+a.y)+(a.z+a.w) + (bvv.x+bvv.y)+(bvv.z+bvv.w);
            ls += __shfl_xor_sync(0xffffffffu, ls, 1);
            ls += __shfl_xor_sync(0xffffffffu, ls, 2);
            *(float4*)&Ss[sr*SS_ + c0] = a;
            *(float4*)&Ss[sr*SS_ + c0 + 4] = bvv;
            if ((t & 3) == 0) {
                float f = __expf(mold - mx);
                rowl[sr] = rowl[sr]*f + ls;
                rowm[sr] = mx;
                rowf[sr] = f;
            }
        }
        __syncthreads();
        // O = O*f + P V
        #pragma unroll
        for (int i = 0; i < 4; i++) {
            u64 f2 = bcast2(rowf[q0 + i]);
            #pragma unroll
            for (int c = 0; c < 4; c++) mul2(oacc[i][c], f2);
        }
        #pragma unroll 2
        for (int kk = 0; kk < 32; kk++) {
            ulonglong2 v0 = *(const ulonglong2*)&Vs[kk*VS_ + pd0];
            ulonglong2 v1 = *(const ulonglong2*)&Vs[kk*VS_ + pd1];
            #pragma unroll
            for (int i = 0; i < 4; i++) {
                u64 p2 = bcast2(Ss[(q0 + i)*SS_ + kk]);
                ffma2(oacc[i][0], p2, v0.x);
                ffma2(oacc[i][1], p2, v0.y);
                ffma2(oacc[i][2], p2, v1.x);
                ffma2(oacc[i][3], p2, v1.y);
            }
        }
    }
    #pragma unroll
    for (int i = 0; i < 4; i++) {
        float inv = 1.f / rowl[q0 + i];
        int row = n0 + q0 + i;
        float2 u0 = unpk(oacc[i][0]), u1 = unpk(oacc[i][1]);
        float2 u2 = unpk(oacc[i][2]), u3 = unpk(oacc[i][3]);
        *(float4*)&outp[(size_t)row*512 + coff + pd0] =
            make_float4(u0.x*inv, u0.y*inv, u1.x*inv, u1.y*inv);
        *(float4*)&outp[(size_t)row*512 + coff + pd1] =
            make_float4(u2.x*inv, u2.y*inv, u3.x*inv, u3.y*inv);
    }
}

// ---------------- launch ----------------
extern "C" void kernel_launch(void* const* d_in, const int* in_sizes, int n_in,
                              void* d_out, int out_size) {
    const float* x          = (const float*)d_in[0];
    const int*   ei         = (const int*)  d_in[1];
    const float* sage_wl    = (const float*)d_in[2];
    const float* sage_wr    = (const float*)d_in[3];
    const float* sage_bl    = (const float*)d_in[4];
    const float* ln_g       = (const float*)d_in[5];
    const float* ln_b       = (const float*)d_in[6];
    const float* conv_w     = (const float*)d_in[7];
    const float* conv_b     = (const float*)d_in[8];
    const float* cnorm_g    = (const float*)d_in[9];
    const float* cnorm_b    = (const float*)d_in[10];
    const float* in_proj_w  = (const float*)d_in[11];
    const float* in_proj_b  = (const float*)d_in[12];
    const float* out_proj_w = (const float*)d_in[13];
    const float* out_proj_b = (const float*)d_in[14];
    const float* anorm_g    = (const float*)d_in[15];
    const float* anorm_b    = (const float*)d_in[16];
    const float* fuse_w     = (const float*)d_in[17];
    const float* fuse_b     = (const float*)d_in[18];
    float* outp = (float*)d_out;

    float *ph, *pagg, *ptmp, *pca, *pcb, *pqkv, *pqkt, *pattn, *po, *po2, *psagew, *pconvw;
    cudaGetSymbolAddress((void**)&ph,     g_h);
    cudaGetSymbolAddress((void**)&pagg,   g_agg);
    cudaGetSymbolAddress((void**)&ptmp,   g_tmp);
    cudaGetSymbolAddress((void**)&pca,    g_ca);
    cudaGetSymbolAddress((void**)&pcb,    g_cb);
    cudaGetSymbolAddress((void**)&pqkv,   g_qkv);
    cudaGetSymbolAddress((void**)&pqkt,   g_qkt);
    cudaGetSymbolAddress((void**)&pattn,  g_attn);
    cudaGetSymbolAddress((void**)&po,     g_o);
    cudaGetSymbolAddress((void**)&po2,    g_o2);
    cudaGetSymbolAddress((void**)&psagew, g_sagew);
    cudaGetSymbolAddress((void**)&pconvw, g_convw);

    // CSR build + weight packing
    k_zero<<<16, 256>>>();
    k_count<<<E_EDGES/256, 256>>>(ei + E_EDGES);
    k_scan<<<1, 1024>>>();
    k_fill<<<E_EDGES/256, 256>>>(ei, ei + E_EDGES);
    k_packsage<<<(6*H*2*H + 255)/256, 256>>>(sage_wl, sage_wr, psagew);
    k_packconv<<<(3*H*3*H + 255)/256, 256>>>(conv_w, pconvw);

    dim3 g_hh(H/BN, N_NODES/BM);   // (2, 64)

    // ---- GNN: 6 SAGE layers ----
    const float* hcur = x;
    for (int i = 0; i < 6; i++) {
        k_agg<<<N_NODES, 256>>>(hcur, pagg);
        k_sgemm<<<g_hh, 256>>>(pagg, H, 0, hcur, H, 0, pagg, H, 0,
                               psagew + (size_t)i*H*2*H, 2*H,
                               ptmp, H, N_NODES, 2*H, H, sage_bl + i*H);
        int flags = (i < 5) ? (F_LN | F_POSTRELU | F_RES) : (F_POSTRELU | F_RES);
        k_ln<<<N_NODES, 256>>>(ptmp, (i < 5) ? ln_g + i*H : nullptr,
                               (i < 5) ? ln_b + i*H : nullptr,
                               hcur, ph, H, flags);
        hcur = ph;
    }

    // ---- CNN branch: 3 conv1d (K=3, pad 1) ----
    const float* cin = ph;
    float* couts[3] = {pca, pcb, pca};
    for (int j = 0; j < 3; j++) {
        k_sgemm<<<g_hh, 256>>>(cin, H, -1, cin, H, 0, cin, H, 1,
                               pconvw + (size_t)j*H*3*H, 3*H,
                               ptmp, H, N_NODES, 3*H, H, conv_b + j*H);
        k_ln<<<N_NODES, 256>>>(ptmp, cnorm_g + j*H, cnorm_b + j*H,
                               nullptr, couts[j], H, F_LN | F_PRERELU);
        cin = couts[j];
    }

    // ---- qkv projection (virtual concat, K = 512) ----
    dim3 g_qkvd(1536/BN, N_NODES/BM);
    k_sgemm<<<g_qkvd, 256>>>(ph, H, 0, cin, H, 0, ph, H, 0,
                             in_proj_w, 512, pqkv, 1536,
                             N_NODES, 512, 1536, in_proj_b);

    // ---- transpose Q,K -> [qk*4+head][d][n] ----
    dim3 g_tr(N_NODES/32, 32);
    k_qkT<<<g_tr, 256>>>(pqkv, pqkt);

    // ---- flash attention ----
    cudaFuncSetAttribute(k_flash, cudaFuncAttributeMaxDynamicSharedMemorySize, FLASH_SMEM);
    dim3 g_fl(64, 4);
    k_flash<<<g_fl, 256, FLASH_SMEM>>>(pqkv, pqkt, pattn);

    // ---- out_proj + LN + fuse ----
    dim3 g_op(512/BN, N_NODES/BM);
    k_sgemm<<<g_op, 256>>>(pattn, 512, 0, pattn + 256, 512, 0, pattn, 512, 0,
                           out_proj_w, 512, po, 512,
                           N_NODES, 512, 512, out_proj_b);
    k_ln<<<N_NODES, 256>>>(po, anorm_g, anorm_b, nullptr, po2, 512, F_LN);
    dim3 g_fu(1, N_NODES/BM);
    k_sgemm<<<g_fu, 256>>>(po2, 512, 0, po2 + 256, 512, 0, po2, 512, 0,
                           fuse_w, 512, outp, 64,
                           N_NODES, 512, 64, fuse_b);
}

// round 7
// speedup vs baseline: 1.4327x; 1.4327x over previous
#include <cuda_runtime.h>
#include <math.h>

#define N_NODES 4096
#define H 256
#define E_EDGES 131072

typedef unsigned long long u64;

__device__ __forceinline__ void ffma2(u64 &d, u64 a, u64 b) {
    asm("fma.rn.f32x2 %0, %1, %2, %0;" : "+l"(d) : "l"(a), "l"(b));
}
__device__ __forceinline__ void mul2(u64 &d, u64 a) {
    asm("mul.rn.f32x2 %0, %0, %1;" : "+l"(d) : "l"(a));
}
__device__ __forceinline__ u64 bcast2(float x) {
    u64 r; asm("mov.b64 %0, {%1, %1};" : "=l"(r) : "f"(x)); return r;
}
__device__ __forceinline__ float2 unpk(u64 v) {
    float2 r; asm("mov.b64 {%0, %1}, %2;" : "=f"(r.x), "=f"(r.y) : "l"(v)); return r;
}

// ---------------- scratch ----------------
__device__ float g_h[N_NODES*H];
__device__ float g_agg[N_NODES*H];
__device__ float g_tmp[N_NODES*H];
__device__ float g_ca[N_NODES*H];
__device__ float g_cb[N_NODES*H];
__device__ float g_qkv[N_NODES*6*H];
__device__ float g_qkt[8*128*N_NODES];   // [qk*4+head][d][n]
__device__ float g_attn[N_NODES*2*H];
__device__ float g_o[N_NODES*2*H];
__device__ float g_o2[N_NODES*2*H];
__device__ float g_sagew[6*H*2*H];
__device__ float g_convw[3*H*3*H];
__device__ int   g_cnt[N_NODES];
__device__ int   g_fillp[N_NODES];
__device__ int   g_off[N_NODES+1];
__device__ int   g_csrs[E_EDGES];
__device__ float g_degf[N_NODES];

// ---------------- CSR build ----------------
__global__ void k_zero() {
    int i = blockIdx.x*256 + threadIdx.x;
    if (i < N_NODES) { g_cnt[i] = 0; g_fillp[i] = 0; }
}
__global__ void k_count(const int* __restrict__ dst) {
    int e = blockIdx.x*256 + threadIdx.x;
    if (e < E_EDGES) atomicAdd(&g_cnt[dst[e]], 1);
}
__global__ void k_scan() {
    __shared__ int ps[1024];
    int t = threadIdx.x;
    int c[4]; int s = 0;
    #pragma unroll
    for (int l = 0; l < 4; l++) { c[l] = g_cnt[t*4+l]; s += c[l]; }
    ps[t] = s;
    __syncthreads();
    for (int d = 1; d < 1024; d <<= 1) {
        int v = (t >= d) ? ps[t-d] : 0;
        __syncthreads();
        ps[t] += v;
        __syncthreads();
    }
    int base = ps[t] - s;
    #pragma unroll
    for (int l = 0; l < 4; l++) {
        g_off[t*4+l] = base;
        base += c[l];
        g_degf[t*4+l] = (float)max(c[l], 1);
    }
    if (t == 1023) g_off[N_NODES] = ps[1023];
}
__global__ void k_fill(const int* __restrict__ src, const int* __restrict__ dst) {
    int e = blockIdx.x*256 + threadIdx.x;
    if (e < E_EDGES) {
        int d = dst[e];
        int p = atomicAdd(&g_fillp[d], 1);
        g_csrs[g_off[d] + p] = src[e];
    }
}

// ---------------- weight packing ----------------
__global__ void k_packsage(const float* __restrict__ wl, const float* __restrict__ wr,
                           float* __restrict__ out) {
    int idx = blockIdx.x*256 + threadIdx.x;
    if (idx < 6*H*2*H) {
        int c = idx & 511;
        int r = idx >> 9;
        out[idx] = (c < H) ? wl[r*H + c] : wr[r*H + (c - H)];
    }
}
__global__ void k_packconv(const float* __restrict__ w, float* __restrict__ out) {
    int idx = blockIdx.x*256 + threadIdx.x;
    if (idx < 3*H*3*H) {
        int c = idx % 768;
        int r = idx / 768;
        int k = c >> 8;
        int i = c & 255;
        out[idx] = w[(size_t)(r*H + i)*3 + k];
    }
}

// ---------------- Q/K transpose ----------------
__global__ __launch_bounds__(256) void k_qkT(const float* __restrict__ qkv,
                                             float* __restrict__ qkt) {
    __shared__ float tile[32][33];
    int nt = blockIdx.x*32;
    int dt = blockIdx.y*32;
    int g  = dt >> 7;
    int cb = (g >> 2)*512 + (g & 3)*128 + (dt & 127);
    int tx = threadIdx.x & 31, ty = threadIdx.x >> 5;
    #pragma unroll
    for (int i = 0; i < 4; i++)
        tile[ty + i*8][tx] = qkv[(size_t)(nt + ty + i*8)*1536 + cb + tx];
    __syncthreads();
    #pragma unroll
    for (int i = 0; i < 4; i++)
        qkt[(size_t)(dt + ty + i*8)*N_NODES + nt + tx] = tile[tx][ty + i*8];
}

// ---------------- mean aggregation ----------------
__global__ __launch_bounds__(256) void k_agg(const float* __restrict__ h,
                                             float* __restrict__ agg) {
    int n = blockIdx.x;
    int f = threadIdx.x;
    int s = g_off[n], e = g_off[n+1];
    __shared__ int nb[256];
    float acc = 0.f;
    for (int base = s; base < e; base += 256) {
        int m = min(256, e - base);
        if (f < m) nb[f] = g_csrs[base + f];
        __syncthreads();
        for (int j = 0; j < m; j++)
            acc += h[(size_t)nb[j]*H + f];
        __syncthreads();
    }
    agg[(size_t)n*H + f] = acc / g_degf[n];
}

// ---------------- segmented SGEMM (f32x2, A-dup, zero-MOV) ----------------
// BM=64, BN=128, BK=16, 256 threads = 16 mg x 16 ng, microtile 4m x 8n (n-paired)
#define BM 64
#define BN 128
#define BK 16
#define ADS 132   // As dup row stride (2*64 + 4)
#define BST 132

__global__ __launch_bounds__(256) void k_sgemm(
    const float* __restrict__ A0, int ld0, int sh0,
    const float* __restrict__ A1, int ld1, int sh1,
    const float* __restrict__ A2, int ld2, int sh2,
    const float* __restrict__ B, int ldb,
    float* __restrict__ C, int ldc,
    int M, int K, int Ncols,
    const float* __restrict__ bias)
{
    __shared__ float As[BK*ADS];    // dup pairs: As[k][2m], (a,a)
    __shared__ float Bs[BK*BST];
    int bm = blockIdx.y * BM;
    int bn = blockIdx.x * BN;
    int t  = threadIdx.x;
    int mg = t >> 4, ng = t & 15;
    int m0  = mg*4;
    int n0a = ng*4;          // split 16B-stride column groups (bank-clean)
    int n0b = 64 + ng*4;

    u64 acc2[4][4];          // [m][npair]; j<2 -> n0a, j>=2 -> n0b
    #pragma unroll
    for (int m = 0; m < 4; m++)
        #pragma unroll
        for (int j = 0; j < 4; j++) acc2[m][j] = 0ULL;

    for (int k0 = 0; k0 < K; k0 += BK) {
        int seg = k0 >> 8;
        const float* A = (seg == 0) ? A0 : (seg == 1) ? A1 : A2;
        int lda = (seg == 0) ? ld0 : (seg == 1) ? ld1 : ld2;
        int sh  = (seg == 0) ? sh0 : (seg == 1) ? sh1 : sh2;
        int kc  = k0 & 255;
        #pragma unroll
        for (int l = 0; l < 4; l++) {
            int flat = t + l*256;
            int ar = flat >> 4, ak = flat & 15;
            int gr = bm + ar + sh;
            float a = (gr >= 0 && gr < M) ? A[(size_t)gr*lda + kc + ak] : 0.f;
            *(float2*)&As[ak*ADS + 2*ar] = make_float2(a, a);
        }
        #pragma unroll
        for (int l = 0; l < 8; l++) {
            int flat = t + l*256;
            int br = flat >> 4, bk = flat & 15;
            int gc = bn + br;
            Bs[bk*BST + br] = (gc < Ncols) ? B[(size_t)gc*ldb + k0 + bk] : 0.f;
        }
        __syncthreads();
        #pragma unroll
        for (int kk = 0; kk < BK; kk++) {
            ulonglong2 ad0 = *(const ulonglong2*)&As[kk*ADS + 2*m0];      // (m0,m0),(m0+1,m0+1)
            ulonglong2 ad1 = *(const ulonglong2*)&As[kk*ADS + 2*m0 + 4];
            ulonglong2 bA  = *(const ulonglong2*)&Bs[kk*BST + n0a];       // (n0a,n0a+1),(n0a+2,n0a+3)
            ulonglong2 bB  = *(const ulonglong2*)&Bs[kk*BST + n0b];
            u64 ap[4] = {ad0.x, ad0.y, ad1.x, ad1.y};
            u64 bp[4] = {bA.x, bA.y, bB.x, bB.y};
            #pragma unroll
            for (int m = 0; m < 4; m++) {
                ffma2(acc2[m][0], ap[m], bp[0]);
                ffma2(acc2[m][1], ap[m], bp[1]);
                ffma2(acc2[m][2], ap[m], bp[2]);
                ffma2(acc2[m][3], ap[m], bp[3]);
            }
        }
        __syncthreads();
    }

    int ca = bn + n0a, cb = bn + n0b;
    float4 bsa = make_float4(0.f,0.f,0.f,0.f), bsb = bsa;
    if (ca < Ncols) bsa = *(const float4*)&bias[ca];
    if (cb < Ncols) bsb = *(const float4*)&bias[cb];
    #pragma unroll
    for (int m = 0; m < 4; m++) {
        int row = bm + m0 + m;
        float2 u0 = unpk(acc2[m][0]), u1 = unpk(acc2[m][1]);
        float2 u2 = unpk(acc2[m][2]), u3 = unpk(acc2[m][3]);
        if (ca < Ncols)
            *(float4*)&C[(size_t)row*ldc + ca] =
                make_float4(u0.x+bsa.x, u0.y+bsa.y, u1.x+bsa.z, u1.y+bsa.w);
        if (cb < Ncols)
            *(float4*)&C[(size_t)row*ldc + cb] =
                make_float4(u2.x+bsb.x, u2.y+bsb.y, u3.x+bsb.z, u3.y+bsb.w);
    }
}

// ---------------- LayerNorm / activation ----------------
#define F_LN       1
#define F_POSTRELU 2
#define F_RES      4
#define F_PRERELU  8

__global__ __launch_bounds__(256) void k_ln(
    const float* __restrict__ x, const float* __restrict__ g, const float* __restrict__ b,
    const float* __restrict__ res, float* __restrict__ out, int W, int flags)
{
    __shared__ float rs[8], rq[8];
    __shared__ float s_mean, s_rstd;
    int row = blockIdx.x, t = threadIdx.x;
    const float* xr = x + (size_t)row*W;
    int two = (W == 512);
    float v0 = xr[t];
    float v1 = two ? xr[t + 256] : 0.f;
    if (flags & F_PRERELU) { v0 = fmaxf(v0, 0.f); v1 = fmaxf(v1, 0.f); }
    float s = v0 + v1, sq = v0*v0 + v1*v1;
    #pragma unroll
    for (int o = 16; o > 0; o >>= 1) {
        s  += __shfl_xor_sync(0xffffffff, s,  o);
        sq += __shfl_xor_sync(0xffffffff, sq, o);
    }
    int warp = t >> 5, lane = t & 31;
    if (lane == 0) { rs[warp] = s; rq[warp] = sq; }
    __syncthreads();
    if (t == 0) {
        float S = 0.f, Q = 0.f;
        #pragma unroll
        for (int w = 0; w < 8; w++) { S += rs[w]; Q += rq[w]; }
        float mean = S / (float)W;
        float var = fmaxf(Q / (float)W - mean*mean, 0.f);
        s_mean = mean;
        s_rstd = rsqrtf(var + 1e-5f);
    }
    __syncthreads();
    float mean = s_mean, rstd = s_rstd;

    float val = v0;
    if (flags & F_LN)       val = (val - mean)*rstd*g[t] + b[t];
    if (flags & F_POSTRELU) val = fmaxf(val, 0.f);
    if (flags & F_RES)      val += res[(size_t)row*W + t];
    out[(size_t)row*W + t] = val;

    if (two) {
        int c = t + 256;
        float val2 = v1;
        if (flags & F_LN)       val2 = (val2 - mean)*rstd*g[c] + b[c];
        if (flags & F_POSTRELU) val2 = fmaxf(val2, 0.f);
        if (flags & F_RES)      val2 += res[(size_t)row*W + c];
        out[(size_t)row*W + c] = val2;
    }
}

// ---------------- flash attention (f32x2, dup operands, zero-MOV) ----------------
// BQ=64, BKV=64, 256 threads = 16 qg x 16 kg.
// QK: per thread 4q x 4k, q from Q-dup (broadcast), k-pairs from Kt.
// PV: per thread 4q x 8d (two 4-col groups), p from S-dup, d-pairs from Vs.
#define QDS 132   // Qtd row stride (128 dup + 4)
#define KTS 68    // Kt  row stride (64 + 4)
#define VSS 132   // Vs  row stride
#define SDS 132   // Sdup row stride (128 dup + 4)
#define OFF_KT (128*QDS)
#define OFF_V  (OFF_KT + 128*KTS)
#define OFF_S  (OFF_V + 64*VSS)
#define OFF_R  (OFF_S + 64*SDS)
#define FLASH_SMEM ((OFF_R + 192)*4)

__global__ __launch_bounds__(256, 1) void k_flash(const float* __restrict__ qkv,
                                                  const float* __restrict__ qkt,
                                                  float* __restrict__ outp)
{
    extern __shared__ float sm[];
    float* Qtd  = sm;            // [128 d][2*64 q dup]
    float* Kt   = sm + OFF_KT;   // [128 d][64 k]
    float* Vs   = sm + OFF_V;    // [64 n][128 d]
    float* Sdup = sm + OFF_S;    // [64 q][2*64 k dup]
    float* rowm = sm + OFF_R;
    float* rowl = rowm + 64;
    float* rowf = rowl + 64;

    int qb = blockIdx.x, head = blockIdx.y, t = threadIdx.x;
    int n0 = qb*64, coff = head*128;
    int qg = t >> 4, kg = t & 15;
    int q0 = qg*4;
    int kqa = 2*kg, kqb = 32 + 2*kg;       // QK k cols (split, bank-clean)
    int pd0 = 4*kg, pd1 = 64 + 4*kg;       // PV d cols (split, bank-clean)

    // ---- load Q dup-transposed: Qtd[d][2q] = (q,q) ----
    const float* Qg = qkt + (size_t)head*128*N_NODES + n0;
    #pragma unroll
    for (int l = 0; l < 8; l++) {
        int f4 = t + l*256;
        int r = f4 >> 4, c = f4 & 15;
        float4 v = *(const float4*)&Qg[(size_t)r*N_NODES + c*4];
        *(float4*)&Qtd[r*QDS + 8*c]     = make_float4(v.x, v.x, v.y, v.y);
        *(float4*)&Qtd[r*QDS + 8*c + 4] = make_float4(v.z, v.z, v.w, v.w);
    }
    if (t < 64) { rowm[t] = -1e30f; rowl[t] = 0.f; }

    u64 oacc[4][4];
    #pragma unroll
    for (int i = 0; i < 4; i++)
        #pragma unroll
        for (int c = 0; c < 4; c++) oacc[i][c] = 0ULL;

    const float scale = 0.08838834764831845f;  // 1/sqrt(128)
    const float* Kg = qkt + (size_t)(4 + head)*128*N_NODES;

    for (int kb = 0; kb < 64; kb++) {
        __syncthreads();
        // ---- load K tile [128 d][64 k] + V tile [64 n][128 d] ----
        #pragma unroll
        for (int l = 0; l < 8; l++) {
            int f4 = t + l*256;
            int r = f4 >> 4, c = f4 & 15;
            *(float4*)&Kt[r*KTS + 4*c] =
                *(const float4*)&Kg[(size_t)r*N_NODES + kb*64 + 4*c];
        }
        #pragma unroll
        for (int l = 0; l < 8; l++) {
            int f4 = t + l*256;
            int r = f4 >> 5, c = f4 & 31;
            *(float4*)&Vs[r*VSS + 4*c] =
                *(const float4*)&qkv[(size_t)(kb*64 + r)*1536 + 1024 + coff + 4*c];
        }
        __syncthreads();
        // ---- S = Q K^T : sacc[q][half] pairs over k ----
        u64 sacc[4][2];
        #pragma unroll
        for (int i = 0; i < 4; i++) { sacc[i][0] = 0ULL; sacc[i][1] = 0ULL; }
        #pragma unroll 4
        for (int d = 0; d < 128; d++) {
            ulonglong2 qa = *(const ulonglong2*)&Qtd[d*QDS + 2*q0];
            ulonglong2 qb2 = *(const ulonglong2*)&Qtd[d*QDS + 2*q0 + 4];
            u64 ka = *(const u64*)&Kt[d*KTS + kqa];
            u64 kb2 = *(const u64*)&Kt[d*KTS + kqb];
            ffma2(sacc[0][0], qa.x,  ka);  ffma2(sacc[0][1], qa.x,  kb2);
            ffma2(sacc[1][0], qa.y,  ka);  ffma2(sacc[1][1], qa.y,  kb2);
            ffma2(sacc[2][0], qb2.x, ka);  ffma2(sacc[2][1], qb2.x, kb2);
            ffma2(sacc[3][0], qb2.y, ka);  ffma2(sacc[3][1], qb2.y, kb2);
        }
        // store S scaled + duplicated: Sdup[q][2k..2k+3] = (s0,s0,s1,s1)
        #pragma unroll
        for (int i = 0; i < 4; i++) {
            float2 ua = unpk(sacc[i][0]);
            float2 ub = unpk(sacc[i][1]);
            *(float4*)&Sdup[(q0+i)*SDS + 4*kg] =
                make_float4(ua.x*scale, ua.x*scale, ua.y*scale, ua.y*scale);
            *(float4*)&Sdup[(q0+i)*SDS + 64 + 4*kg] =
                make_float4(ub.x*scale, ub.x*scale, ub.y*scale, ub.y*scale);
        }
        __syncthreads();
        // ---- online softmax: 4 threads/row; 16B-stride access (bank-clean) ----
        {
            int sr = t >> 2, cc = (t & 3)*4;
            float4 v[8];
            float mold = rowm[sr];
            float mx = mold;
            #pragma unroll
            for (int u2 = 0; u2 < 8; u2++) {
                v[u2] = *(float4*)&Sdup[sr*SDS + cc + u2*16];
                mx = fmaxf(mx, fmaxf(v[u2].x, v[u2].z));
            }
            mx = fmaxf(mx, __shfl_xor_sync(0xffffffffu, mx, 1));
            mx = fmaxf(mx, __shfl_xor_sync(0xffffffffu, mx, 2));
            float ls = 0.f;
            #pragma unroll
            for (int u2 = 0; u2 < 8; u2++) {
                float e0 = __expf(v[u2].x - mx);
                float e1 = __expf(v[u2].z - mx);
                ls += e0 + e1;
                *(float4*)&Sdup[sr*SDS + cc + u2*16] = make_float4(e0, e0, e1, e1);
            }
            ls += __shfl_xor_sync(0xffffffffu, ls, 1);
            ls += __shfl_xor_sync(0xffffffffu, ls, 2);
            if ((t & 3) == 0) {
                float f = __expf(mold - mx);
                rowl[sr] = rowl[sr]*f + ls;
                rowm[sr] = mx;
                rowf[sr] = f;
            }
        }
        __syncthreads();
        // ---- O = O*f + P V ----
        #pragma unroll
        for (int i = 0; i < 4; i++) {
            u64 f2 = bcast2(rowf[q0 + i]);
            #pragma unroll
            for (int c = 0; c < 4; c++) mul2(oacc[i][c], f2);
        }
        #pragma unroll 2
        for (int kk = 0; kk < 64; kk++) {
            ulonglong2 v0 = *(const ulonglong2*)&Vs[kk*VSS + pd0];
            ulonglong2 v1 = *(const ulonglong2*)&Vs[kk*VSS + pd1];
            #pragma unroll
            for (int i = 0; i < 4; i++) {
                u64 p2 = *(const u64*)&Sdup[(q0+i)*SDS + 2*kk];
                ffma2(oacc[i][0], p2, v0.x);
                ffma2(oacc[i][1], p2, v0.y);
                ffma2(oacc[i][2], p2, v1.x);
                ffma2(oacc[i][3], p2, v1.y);
            }
        }
    }
    #pragma unroll
    for (int i = 0; i < 4; i++) {
        float inv = 1.f / rowl[q0 + i];
        int row = n0 + q0 + i;
        float2 u0 = unpk(oacc[i][0]), u1 = unpk(oacc[i][1]);
        float2 u2 = unpk(oacc[i][2]), u3 = unpk(oacc[i][3]);
        *(float4*)&outp[(size_t)row*512 + coff + pd0] =
            make_float4(u0.x*inv, u0.y*inv, u1.x*inv, u1.y*inv);
        *(float4*)&outp[(size_t)row*512 + coff + pd1] =
            make_float4(u2.x*inv, u2.y*inv, u3.x*inv, u3.y*inv);
    }
}

// ---------------- launch ----------------
extern "C" void kernel_launch(void* const* d_in, const int* in_sizes, int n_in,
                              void* d_out, int out_size) {
    const float* x          = (const float*)d_in[0];
    const int*   ei         = (const int*)  d_in[1];
    const float* sage_wl    = (const float*)d_in[2];
    const float* sage_wr    = (const float*)d_in[3];
    const float* sage_bl    = (const float*)d_in[4];
    const float* ln_g       = (const float*)d_in[5];
    const float* ln_b       = (const float*)d_in[6];
    const float* conv_w     = (const float*)d_in[7];
    const float* conv_b     = (const float*)d_in[8];
    const float* cnorm_g    = (const float*)d_in[9];
    const float* cnorm_b    = (const float*)d_in[10];
    const float* in_proj_w  = (const float*)d_in[11];
    const float* in_proj_b  = (const float*)d_in[12];
    const float* out_proj_w = (const float*)d_in[13];
    const float* out_proj_b = (const float*)d_in[14];
    const float* anorm_g    = (const float*)d_in[15];
    const float* anorm_b    = (const float*)d_in[16];
    const float* fuse_w     = (const float*)d_in[17];
    const float* fuse_b     = (const float*)d_in[18];
    float* outp = (float*)d_out;

    float *ph, *pagg, *ptmp, *pca, *pcb, *pqkv, *pqkt, *pattn, *po, *po2, *psagew, *pconvw;
    cudaGetSymbolAddress((void**)&ph,     g_h);
    cudaGetSymbolAddress((void**)&pagg,   g_agg);
    cudaGetSymbolAddress((void**)&ptmp,   g_tmp);
    cudaGetSymbolAddress((void**)&pca,    g_ca);
    cudaGetSymbolAddress((void**)&pcb,    g_cb);
    cudaGetSymbolAddress((void**)&pqkv,   g_qkv);
    cudaGetSymbolAddress((void**)&pqkt,   g_qkt);
    cudaGetSymbolAddress((void**)&pattn,  g_attn);
    cudaGetSymbolAddress((void**)&po,     g_o);
    cudaGetSymbolAddress((void**)&po2,    g_o2);
    cudaGetSymbolAddress((void**)&psagew, g_sagew);
    cudaGetSymbolAddress((void**)&pconvw, g_convw);

    // CSR build + weight packing
    k_zero<<<16, 256>>>();
    k_count<<<E_EDGES/256, 256>>>(ei + E_EDGES);
    k_scan<<<1, 1024>>>();
    k_fill<<<E_EDGES/256, 256>>>(ei, ei + E_EDGES);
    k_packsage<<<(6*H*2*H + 255)/256, 256>>>(sage_wl, sage_wr, psagew);
    k_packconv<<<(3*H*3*H + 255)/256, 256>>>(conv_w, pconvw);

    dim3 g_hh(H/BN, N_NODES/BM);   // (2, 64)

    // ---- GNN: 6 SAGE layers ----
    const float* hcur = x;
    for (int i = 0; i < 6; i++) {
        k_agg<<<N_NODES, 256>>>(hcur, pagg);
        k_sgemm<<<g_hh, 256>>>(pagg, H, 0, hcur, H, 0, pagg, H, 0,
                               psagew + (size_t)i*H*2*H, 2*H,
                               ptmp, H, N_NODES, 2*H, H, sage_bl + i*H);
        int flags = (i < 5) ? (F_LN | F_POSTRELU | F_RES) : (F_POSTRELU | F_RES);
        k_ln<<<N_NODES, 256>>>(ptmp, (i < 5) ? ln_g + i*H : nullptr,
                               (i < 5) ? ln_b + i*H : nullptr,
                               hcur, ph, H, flags);
        hcur = ph;
    }

    // ---- CNN branch ----
    const float* cin = ph;
    float* couts[3] = {pca, pcb, pca};
    for (int j = 0; j < 3; j++) {
        k_sgemm<<<g_hh, 256>>>(cin, H, -1, cin, H, 0, cin, H, 1,
                               pconvw + (size_t)j*H*3*H, 3*H,
                               ptmp, H, N_NODES, 3*H, H, conv_b + j*H);
        k_ln<<<N_NODES, 256>>>(ptmp, cnorm_g + j*H, cnorm_b + j*H,
                               nullptr, couts[j], H, F_LN | F_PRERELU);
        cin = couts[j];
    }

    // ---- qkv projection ----
    dim3 g_qkvd(1536/BN, N_NODES/BM);
    k_sgemm<<<g_qkvd, 256>>>(ph, H, 0, cin, H, 0, ph, H, 0,
                             in_proj_w, 512, pqkv, 1536,
                             N_NODES, 512, 1536, in_proj_b);

    // ---- transpose Q,K ----
    dim3 g_tr(N_NODES/32, 32);
    k_qkT<<<g_tr, 256>>>(pqkv, pqkt);

    // ---- flash attention ----
    cudaFuncSetAttribute(k_flash, cudaFuncAttributeMaxDynamicSharedMemorySize, FLASH_SMEM);
    dim3 g_fl(64, 4);
    k_flash<<<g_fl, 256, FLASH_SMEM>>>(pqkv, pqkt, pattn);

    // ---- out_proj + LN + fuse ----
    dim3 g_op(512/BN, N_NODES/BM);
    k_sgemm<<<g_op, 256>>>(pattn, 512, 0, pattn + 256, 512, 0, pattn, 512, 0,
                           out_proj_w, 512, po, 512,
                           N_NODES, 512, 512, out_proj_b);
    k_ln<<<N_NODES, 256>>>(po, anorm_g, anorm_b, nullptr, po2, 512, F_LN);
    dim3 g_fu(1, N_NODES/BM);
    k_sgemm<<<g_fu, 256>>>(po2, 512, 0, po2 + 256, 512, 0, po2, 512, 0,
                           fuse_w, 512, outp, 64,
                           N_NODES, 512, 64, fuse_b);
}